// round 17
// baseline (speedup 1.0000x reference)
#include <cuda_runtime.h>
#include <cuda_fp16.h>
#include <cstdint>

#define B 32
#define S 4096
#define H 512

// ---------------- scratch (no allocs allowed) ----------------
__device__ float g_dec_proj[B * H];
__device__ float g_pctx[16][B * H];
__device__ __align__(16) __half g_Wh[H * H];              // W_enc^T fp16, [n][k]
__device__ __align__(16) __half g_Eh[(size_t)B * S * H];  // E fp16 (written by k_score)

// ---------------- helpers ----------------
__device__ __forceinline__ uint32_t smem_u32(const void* p) {
    uint32_t a;
    asm("{ .reg .u64 t; cvta.to.shared.u64 t, %1; cvt.u32.u64 %0, t; }" : "=r"(a) : "l"(p));
    return a;
}
// fast tanh: 1 - 2/(exp2(2x/ln2)+1) via MUFU (abs err ~1e-7)
__device__ __forceinline__ float tanh_fast(float x) {
    float e, r;
    asm("ex2.approx.f32 %0, %1;" : "=f"(e) : "f"(x * 2.8853900817779268f));
    asm("rcp.approx.f32 %0, %1;" : "=f"(r) : "f"(e + 1.0f));
    return 1.0f - 2.0f * r;
}
__device__ __forceinline__ void cp16(uint32_t dst, const void* src) {
    asm volatile("cp.async.ca.shared.global [%0], [%1], 16;" :: "r"(dst), "l"(src));
}
__device__ __forceinline__ void ldsm4(uint32_t* r, uint32_t a) {
    asm volatile("ldmatrix.sync.aligned.m8n8.x4.shared.b16 {%0,%1,%2,%3}, [%4];"
                 : "=r"(r[0]), "=r"(r[1]), "=r"(r[2]), "=r"(r[3]) : "r"(a));
}
__device__ __forceinline__ void mma16816(float* d, const uint32_t* a,
                                         uint32_t b0, uint32_t b1) {
    asm volatile(
        "mma.sync.aligned.m16n8k16.row.col.f32.f16.f16.f32 "
        "{%0,%1,%2,%3}, {%4,%5,%6,%7}, {%8,%9}, {%0,%1,%2,%3};"
        : "+f"(d[0]), "+f"(d[1]), "+f"(d[2]), "+f"(d[3])
        : "r"(a[0]), "r"(a[1]), "r"(a[2]), "r"(a[3]), "r"(b0), "r"(b1));
}
__device__ __forceinline__ uint4 cvt8(float4 a, float4 b) {
    __half2 h0 = __floats2half2_rn(a.x, a.y);
    __half2 h1 = __floats2half2_rn(a.z, a.w);
    __half2 h2 = __floats2half2_rn(b.x, b.y);
    __half2 h3 = __floats2half2_rn(b.z, b.w);
    return make_uint4(*(uint32_t*)&h0, *(uint32_t*)&h1,
                      *(uint32_t*)&h2, *(uint32_t*)&h3);
}

// ---------------- SMEM layout for k_score ----------------
// stage (48KB): [A 128 rows x 128B = 16K][B 256 rows x 128B = 32K], 3 stages
#define ST_SZ 49152
#define SDPB  147456
#define SWV   149504
#define SRED  151552
#define SMEM_SZ 153600

// ---------------------------------------------------------------------------
// Kernel 0: fused prep. Blocks 0..255: transpose W_enc -> g_Wh fp16 ([n][k]).
// Blocks 256..287: dec_proj (256 threads, 2 outputs each).
// ---------------------------------------------------------------------------
__global__ void __launch_bounds__(256) k_prep(const float* __restrict__ W,
                                              const float* __restrict__ dh,
                                              const float* __restrict__ Wd,
                                              const float* __restrict__ bd) {
    if (blockIdx.x < 256) {
        __shared__ float t[32][33];
        int tx = threadIdx.x & 31, ty = threadIdx.x >> 5;
        int k0 = (blockIdx.x & 15) * 32, h0 = (blockIdx.x >> 4) * 32;
#pragma unroll
        for (int q = 0; q < 4; ++q)
            t[ty + q * 8][tx] = W[(size_t)(h0 + ty + q * 8) * H + k0 + tx];
        __syncthreads();
#pragma unroll
        for (int q = 0; q < 4; ++q) {
            float v = t[tx][ty + q * 8];
            g_Wh[(size_t)(k0 + ty + q * 8) * H + h0 + tx] = __float2half(v);
        }
    } else {
        __shared__ float s_dh[H];
        int b = blockIdx.x - 256;
        int t = threadIdx.x;
        s_dh[t] = dh[b * H + t];
        s_dh[t + 256] = dh[b * H + t + 256];
        __syncthreads();
#pragma unroll
        for (int rep = 0; rep < 2; ++rep) {
            int k = t + rep * 256;
            float acc = bd[k];
#pragma unroll 8
            for (int h = 0; h < H; ++h) acc += s_dh[h] * Wd[h * H + k];
            g_dec_proj[b * H + k] = acc;
        }
    }
}

// ---------------------------------------------------------------------------
// Kernel 2: HMMA fused score. 512 threads, 16 warps (4m x 4n), warp m32 x n64.
// CTA M=128, N in 2 chunks of 256, K in 8 chunks of 64. 3-stage ring.
// A: LDG fp32 E -> cvt fp16 -> STS (+ STG to g_Eh once). B: cp.async of g_Wh.
// ---------------------------------------------------------------------------
__global__ void __launch_bounds__(512, 1) k_score(
    const float* __restrict__ E, const float* __restrict__ be,
    const float* __restrict__ Wvv, const float* __restrict__ bv,
    float* __restrict__ scores) {
    extern __shared__ char smem[];
    uint32_t sb = smem_u32(smem);
    int tid = threadIdx.x;
    int lane = tid & 31, w = tid >> 5;
    int wm = w & 3, wn = w >> 2;
    int m0blk = blockIdx.x * 128;
    int b = m0blk >> 12;

    float* sDPB = (float*)(smem + SDPB);
    float* sWv  = (float*)(smem + SWV);
    float* sRed = (float*)(smem + SRED);   // [4][128]
    sDPB[tid] = g_dec_proj[b * H + tid] + be[tid];
    sWv[tid]  = Wvv[tid];

    // ---- A path: fp32 LDG + cvt + STS/STG. thread: row=tid>>2, chunks ac, ac+4 ----
    int ar = tid >> 2, ac = tid & 3;
    const float* aptr = E + (size_t)(m0blk + ar) * H;       // fp32 row
    __half* ehp = g_Eh + (size_t)(m0blk + ar) * H;          // fp16 row (out)
    uint32_t adst0 = (uint32_t)(ar * 128) + (((uint32_t)(ac       ^ (ar & 7))) << 4);
    uint32_t adst1 = (uint32_t)(ar * 128) + (((uint32_t)((ac + 4) ^ (ar & 7))) << 4);
    // ---- B path: cp.async; thread: row=tid>>1, chunks bc0..bc0+3 ----
    int br = tid >> 1, bc0 = (tid & 1) * 4;
    const char* bptr = (const char*)(g_Wh + (size_t)br * H) + bc0 * 16;
    uint32_t bdst[4];
#pragma unroll
    for (int q = 0; q < 4; ++q)
        bdst[q] = 16384u + (uint32_t)(br * 128) + (((uint32_t)((bc0 + q) ^ (br & 7))) << 4);

    // prologue: stages 0,1  (nc = 0, kc = s)
#pragma unroll
    for (int s = 0; s < 2; ++s) {
        uint32_t dbase = sb + s * ST_SZ;
        const char* bsrc = bptr + s * 128;
#pragma unroll
        for (int q = 0; q < 4; ++q) cp16(dbase + bdst[q], bsrc + q * 16);
        asm volatile("cp.async.commit_group;" ::: "memory");
        const float* asrc = aptr + s * 64;
        float4 x0 = *(const float4*)(asrc + ac * 8);
        float4 x1 = *(const float4*)(asrc + ac * 8 + 4);
        float4 y0 = *(const float4*)(asrc + (ac + 4) * 8);
        float4 y1 = *(const float4*)(asrc + (ac + 4) * 8 + 4);
        uint4 c0 = cvt8(x0, x1), c1 = cvt8(y0, y1);
        *(uint4*)(smem + s * ST_SZ + adst0) = c0;
        *(uint4*)(smem + s * ST_SZ + adst1) = c1;
        *(uint4*)(ehp + s * 64 + ac * 8)       = c0;   // persist fp16 E
        *(uint4*)(ehp + s * 64 + (ac + 4) * 8) = c1;
    }

    // ---- ldsm offsets (kk=0); kk advances via XOR (kk<<5) ----
    int mat = lane >> 3, rl = lane & 7;
    int ch0 = mat >> 1;
    uint32_t offA[2], offB[4];
#pragma unroll
    for (int mi = 0; mi < 2; ++mi) {
        int row = wm * 32 + mi * 16 + (mat & 1) * 8 + rl;
        offA[mi] = (uint32_t)(row * 128) + (((uint32_t)(ch0 ^ (row & 7))) << 4);
    }
#pragma unroll
    for (int nt = 0; nt < 4; ++nt) {
        int row = wn * 64 + nt * 16 + (mat & 1) * 8 + rl;
        offB[nt] = 16384u + (uint32_t)(row * 128) + (((uint32_t)(ch0 ^ (row & 7))) << 4);
    }

    float acc[2][8][4];
#pragma unroll
    for (int mi = 0; mi < 2; ++mi)
#pragma unroll
        for (int nj = 0; nj < 8; ++nj)
#pragma unroll
            for (int q = 0; q < 4; ++q) acc[mi][nj][q] = 0.f;
    float p[4] = {0.f, 0.f, 0.f, 0.f};

#pragma unroll 1
    for (int s = 0; s < 16; ++s) {
        if (s < 15) { asm volatile("cp.async.wait_group 1;" ::: "memory"); }
        else        { asm volatile("cp.async.wait_group 0;" ::: "memory"); }
        __syncthreads();

        float4 x0, x1, y0, y1;
        int s2 = s + 2;
        bool pf = (s2 < 16);
        uint32_t pbase = (uint32_t)((s2 % 3) * ST_SZ);
        int kc2 = s2 & 7;
        if (pf) {
            int nc2 = s2 >> 3;
            // B prefetch (N-chunk stride: 256 rows x 1024 B/row = 262144 B)
            const char* bsrc = bptr + nc2 * 262144 + kc2 * 128;
#pragma unroll
            for (int q = 0; q < 4; ++q) cp16(sb + pbase + bdst[q], bsrc + q * 16);
            asm volatile("cp.async.commit_group;" ::: "memory");
            // A fp32 LDG (converted + STS'd after the MMA block)
            const float* asrc = aptr + kc2 * 64;
            x0 = *(const float4*)(asrc + ac * 8);
            x1 = *(const float4*)(asrc + ac * 8 + 4);
            y0 = *(const float4*)(asrc + (ac + 4) * 8);
            y1 = *(const float4*)(asrc + (ac + 4) * 8 + 4);
        }

        int nc = s >> 3, kc = s & 7;
        uint32_t abase = sb + (s % 3) * ST_SZ;

#pragma unroll
        for (int kk = 0; kk < 4; ++kk) {
            uint32_t xr = ((uint32_t)kk) << 5;
            uint32_t ah[2][4], bh[4][4];
#pragma unroll
            for (int mi = 0; mi < 2; ++mi) ldsm4(ah[mi], abase + (offA[mi] ^ xr));
#pragma unroll
            for (int nt = 0; nt < 4; ++nt) ldsm4(bh[nt], abase + (offB[nt] ^ xr));
#pragma unroll
            for (int mi = 0; mi < 2; ++mi)
#pragma unroll
                for (int nt = 0; nt < 4; ++nt) {
                    mma16816(acc[mi][nt * 2],     ah[mi], bh[nt][0], bh[nt][2]);
                    mma16816(acc[mi][nt * 2 + 1], ah[mi], bh[nt][1], bh[nt][3]);
                }
        }

        if (pf) {   // A cvt + STS into stage (s+2)%3; STG once (first N-chunk)
            uint4 c0 = cvt8(x0, x1), c1 = cvt8(y0, y1);
            *(uint4*)(smem + pbase + adst0) = c0;
            *(uint4*)(smem + pbase + adst1) = c1;
            if (s2 < 8) {
                *(uint4*)(ehp + kc2 * 64 + ac * 8)       = c0;
                *(uint4*)(ehp + kc2 * 64 + (ac + 4) * 8) = c1;
            }
        }

        if (kc == 7) {   // end of N-chunk: fold into score partials
#pragma unroll
            for (int mi = 0; mi < 2; ++mi)
#pragma unroll
                for (int nj = 0; nj < 8; ++nj) {
                    int c0 = nc * 256 + wn * 64 + nj * 8 + (lane & 3) * 2;
                    float d0 = sDPB[c0], d1 = sDPB[c0 + 1];
                    float v0 = sWv[c0],  v1 = sWv[c0 + 1];
                    p[mi * 2]     += tanh_fast(acc[mi][nj][0] + d0) * v0
                                   + tanh_fast(acc[mi][nj][1] + d1) * v1;
                    p[mi * 2 + 1] += tanh_fast(acc[mi][nj][2] + d0) * v0
                                   + tanh_fast(acc[mi][nj][3] + d1) * v1;
#pragma unroll
                    for (int q = 0; q < 4; ++q) acc[mi][nj][q] = 0.f;
                }
        }
    }

    // reduce over lane&3 (4 col groups within warp)
#pragma unroll
    for (int i = 0; i < 4; ++i) {
        p[i] += __shfl_xor_sync(~0u, p[i], 1);
        p[i] += __shfl_xor_sync(~0u, p[i], 2);
    }
    if ((lane & 3) == 0) {
        int g = lane >> 2;
        sRed[wn * 128 + wm * 32 + g]      = p[0];   // mi=0 rows
        sRed[wn * 128 + wm * 32 + 8 + g]  = p[1];
        sRed[wn * 128 + wm * 32 + 16 + g] = p[2];   // mi=1 rows
        sRed[wn * 128 + wm * 32 + 24 + g] = p[3];
    }
    __syncthreads();
    if (tid < 128) {
        float bvv = __ldg(bv);
        scores[m0blk + tid] = sRed[tid] + sRed[128 + tid] + sRed[256 + tid] +
                              sRed[384 + tid] + bvv;
    }
}

// ---------------------------------------------------------------------------
// Kernel 3: in-place softmax over S per batch
// ---------------------------------------------------------------------------
__global__ void __launch_bounds__(1024) k_softmax(float* __restrict__ w) {
    __shared__ float red[32];
    int b = blockIdx.x, tid = threadIdx.x;
    float* p = w + b * S;
    float v[4];
    float m = -1e30f;
#pragma unroll
    for (int i = 0; i < 4; ++i) { v[i] = p[tid + i * 1024]; m = fmaxf(m, v[i]); }
#pragma unroll
    for (int off = 16; off; off >>= 1) m = fmaxf(m, __shfl_xor_sync(~0u, m, off));
    if ((tid & 31) == 0) red[tid >> 5] = m;
    __syncthreads();
    if (tid < 32) {
        float t = red[tid];
#pragma unroll
        for (int off = 16; off; off >>= 1) t = fmaxf(t, __shfl_xor_sync(~0u, t, off));
        if (tid == 0) red[0] = t;
    }
    __syncthreads();
    m = red[0];
    __syncthreads();
    float s = 0.f;
#pragma unroll
    for (int i = 0; i < 4; ++i) { v[i] = expf(v[i] - m); s += v[i]; }
#pragma unroll
    for (int off = 16; off; off >>= 1) s += __shfl_xor_sync(~0u, s, off);
    if ((tid & 31) == 0) red[tid >> 5] = s;
    __syncthreads();
    if (tid < 32) {
        float t = red[tid];
#pragma unroll
        for (int off = 16; off; off >>= 1) t += __shfl_xor_sync(~0u, t, off);
        if (tid == 0) red[0] = t;
    }
    __syncthreads();
    float inv = 1.0f / red[0];
#pragma unroll
    for (int i = 0; i < 4; ++i) p[tid + i * 1024] = v[i] * inv;
}

// ---------------------------------------------------------------------------
// Kernel 4: context partials from fp16 E (half the DRAM traffic)
// ---------------------------------------------------------------------------
__global__ void __launch_bounds__(64) k_ctx_partial(const float* __restrict__ w) {
    int b = blockIdx.y, sc = blockIdx.x;
    const uint4* Eb = (const uint4*)(g_Eh + ((size_t)b * S + (size_t)sc * 256) * H)
                      + threadIdx.x;
    const float* wb = w + b * S + sc * 256;
    float acc[8];
#pragma unroll
    for (int j = 0; j < 8; ++j) acc[j] = 0.f;
#pragma unroll 4
    for (int s = 0; s < 256; ++s) {
        float ws = __ldg(wb + s);
        uint4 e = Eb[(size_t)s * 64];
        float2 f0 = __half22float2(*(__half2*)&e.x);
        float2 f1 = __half22float2(*(__half2*)&e.y);
        float2 f2 = __half22float2(*(__half2*)&e.z);
        float2 f3 = __half22float2(*(__half2*)&e.w);
        acc[0] += ws * f0.x; acc[1] += ws * f0.y;
        acc[2] += ws * f1.x; acc[3] += ws * f1.y;
        acc[4] += ws * f2.x; acc[5] += ws * f2.y;
        acc[6] += ws * f3.x; acc[7] += ws * f3.y;
    }
    float* dst = &g_pctx[sc][b * H] + threadIdx.x * 8;
    *(float4*)dst       = make_float4(acc[0], acc[1], acc[2], acc[3]);
    *(float4*)(dst + 4) = make_float4(acc[4], acc[5], acc[6], acc[7]);
}

__global__ void __launch_bounds__(256) k_ctx_reduce(float* __restrict__ ctx) {
    int i = blockIdx.x * 256 + threadIdx.x;
    float a = 0.f;
#pragma unroll
    for (int k = 0; k < 16; ++k) a += g_pctx[k][i];
    ctx[i] = a;
}

// ---------------------------------------------------------------------------
extern "C" void kernel_launch(void* const* d_in, const int* in_sizes, int n_in,
                              void* d_out, int out_size) {
    const float* E  = (const float*)d_in[0];
    const float* dh = (const float*)d_in[1];
    const float* We = (const float*)d_in[2];
    const float* be = (const float*)d_in[3];
    const float* Wd = (const float*)d_in[4];
    const float* bd = (const float*)d_in[5];
    const float* Wv = (const float*)d_in[6];
    const float* bv = (const float*)d_in[7];
    float* out = (float*)d_out;
    float* ctx = out;
    float* wts = out + B * H;

    cudaFuncSetAttribute(k_score, cudaFuncAttributeMaxDynamicSharedMemorySize, SMEM_SZ);

    k_prep<<<288, 256>>>(We, dh, Wd, bd);
    k_score<<<(B * S) / 128, 512, SMEM_SZ>>>(E, be, Wv, bv, wts);
    k_softmax<<<B, 1024>>>(wts);
    k_ctx_partial<<<dim3(16, B), 64>>>(wts);
    k_ctx_reduce<<<(B * H) / 256, 256>>>(ctx);
}